// round 7
// baseline (speedup 1.0000x reference)
#include <cuda_runtime.h>

#define NNODES 50000
#define NEDGES 800000
#define FDIM   128
#define F3     384
#define RBFN   20
#define RCUT   5.0f
#define PI_F   3.14159265358979f

// Scratch (static __device__ — no allocations)
__device__ float  g_phi[(size_t)NNODES * F3];     // per-node phi (76.8 MB)
__device__ float4 g_sorted[NEDGES];               // dst-sorted {rx,ry,rz,src-bits}
__device__ int    g_cnt[NNODES];
__device__ int    g_offs[NNODES + 1];
__device__ int    g_cursor[NNODES];

// ---------------------------------------------------------------------------
// Sort pipeline: zero -> histogram -> scan -> scatter
// ---------------------------------------------------------------------------
__global__ void zero_cnt_kernel() {
    int i = blockIdx.x * blockDim.x + threadIdx.x;
    if (i < NNODES) g_cnt[i] = 0;
}

__global__ void hist_kernel(const int2* __restrict__ eidx) {
    int e = blockIdx.x * blockDim.x + threadIdx.x;
    if (e < NEDGES) atomicAdd(&g_cnt[eidx[e].x], 1);
}

__device__ __forceinline__ int warp_incl_scan(int v, int lane) {
    #pragma unroll
    for (int o = 1; o < 32; o <<= 1) {
        int u = __shfl_up_sync(0xffffffffu, v, o);
        if (lane >= o) v += u;
    }
    return v;
}

__global__ __launch_bounds__(1024) void scan_kernel() {
    __shared__ int swarp[32];
    __shared__ int s_run;
    const int t = threadIdx.x, lane = t & 31, wid = t >> 5;
    if (t == 0) s_run = 0;
    __syncthreads();
    for (int base = 0; base < NNODES; base += 1024) {
        int c = (base + t < NNODES) ? g_cnt[base + t] : 0;
        int incl = warp_incl_scan(c, lane);
        if (lane == 31) swarp[wid] = incl;
        __syncthreads();
        if (wid == 0) swarp[lane] = warp_incl_scan(swarp[lane], lane);
        __syncthreads();
        int add = (wid > 0) ? swarp[wid - 1] : 0;
        int run0 = s_run;
        int excl = run0 + add + incl - c;
        if (base + t < NNODES) { g_offs[base + t] = excl; g_cursor[base + t] = excl; }
        __syncthreads();
        if (t == 0) s_run = run0 + swarp[31];
        __syncthreads();
    }
    if (t == 0) g_offs[NNODES] = NEDGES;
}

__global__ void scatter_kernel(const int2* __restrict__ eidx,
                               const float* __restrict__ rvec) {
    int e = blockIdx.x * blockDim.x + threadIdx.x;
    if (e >= NEDGES) return;
    int2 de = eidx[e];
    int pos = atomicAdd(&g_cursor[de.x], 1);
    g_sorted[pos] = make_float4(rvec[3 * e + 0], rvec[3 * e + 1],
                                rvec[3 * e + 2], __int_as_float(de.y));
}

// ---------------------------------------------------------------------------
// phi_kernel: per-node fused MLP (unchanged from round 2; measured-good)
// ---------------------------------------------------------------------------
__device__ __forceinline__ void mm_tile_128(const float* __restrict__ Xs,
                                            const float* __restrict__ Ws,
                                            int r0, int tc, float acc[8][8]) {
    #pragma unroll 4
    for (int k = 0; k < 128; k++) {
        float a[8];
        #pragma unroll
        for (int i = 0; i < 8; i++) a[i] = Xs[(r0 + i) * 128 + k];
        float4 bA = ((const float4*)Ws)[k * 32 + tc * 2];
        float4 bB = ((const float4*)Ws)[k * 32 + tc * 2 + 1];
        float b[8] = {bA.x, bA.y, bA.z, bA.w, bB.x, bB.y, bB.z, bB.w};
        #pragma unroll
        for (int i = 0; i < 8; i++)
            #pragma unroll
            for (int j = 0; j < 8; j++)
                acc[i][j] = fmaf(a[i], b[j], acc[i][j]);
    }
}

__global__ __launch_bounds__(256) void phi_kernel(
        const float* __restrict__ X,
        const float* __restrict__ W1,
        const float* __restrict__ b1,
        const float* __restrict__ W2,
        const float* __restrict__ b2) {
    extern __shared__ float sm[];
    float* Xs = sm;
    float* Ws = sm + 16384;
    const int tid  = threadIdx.x;
    const int row0 = blockIdx.x * 128;

    {
        const float4* X4  = (const float4*)X;
        const float4* W14 = (const float4*)W1;
        float4* Xs4 = (float4*)Xs;
        float4* Ws4 = (float4*)Ws;
        #pragma unroll
        for (int t = 0; t < 16; t++) {
            int i = tid + t * 256;
            int r = i >> 5, c = i & 31;
            int gr = row0 + r;
            float4 v = make_float4(0.f, 0.f, 0.f, 0.f);
            if (gr < NNODES) v = X4[gr * 32 + c];
            Xs4[i] = v;
        }
        #pragma unroll
        for (int t = 0; t < 16; t++) {
            int i = tid + t * 256;
            Ws4[i] = W14[i];
        }
    }
    __syncthreads();

    const int tr = tid >> 4, tc = tid & 15;
    const int r0 = tr * 8,  c0 = tc * 8;

    float acc[8][8];
    #pragma unroll
    for (int i = 0; i < 8; i++)
        #pragma unroll
        for (int j = 0; j < 8; j++) acc[i][j] = 0.f;

    mm_tile_128(Xs, Ws, r0, tc, acc);
    __syncthreads();

    #pragma unroll
    for (int j = 0; j < 8; j++) {
        float bias = b1[c0 + j];
        #pragma unroll
        for (int i = 0; i < 8; i++) {
            float v = acc[i][j] + bias;
            Xs[(r0 + i) * 128 + c0 + j] = v / (1.f + __expf(-v));
        }
    }
    __syncthreads();

    const float4* W24 = (const float4*)W2;
    for (int ch = 0; ch < 3; ch++) {
        {
            float4* Ws4 = (float4*)Ws;
            #pragma unroll
            for (int t = 0; t < 16; t++) {
                int i = tid + t * 256;
                int k = i >> 5, c = i & 31;
                Ws4[i] = W24[k * 96 + ch * 32 + c];
            }
        }
        __syncthreads();

        float acc2[8][8];
        #pragma unroll
        for (int i = 0; i < 8; i++)
            #pragma unroll
            for (int j = 0; j < 8; j++) acc2[i][j] = 0.f;

        mm_tile_128(Xs, Ws, r0, tc, acc2);

        float bb[8];
        #pragma unroll
        for (int j = 0; j < 8; j++) bb[j] = b2[ch * 128 + c0 + j];

        #pragma unroll
        for (int i = 0; i < 8; i++) {
            int gr = row0 + r0 + i;
            if (gr < NNODES) {
                float4 o0 = make_float4(acc2[i][0] + bb[0], acc2[i][1] + bb[1],
                                        acc2[i][2] + bb[2], acc2[i][3] + bb[3]);
                float4 o1 = make_float4(acc2[i][4] + bb[4], acc2[i][5] + bb[5],
                                        acc2[i][6] + bb[6], acc2[i][7] + bb[7]);
                float4* dst = (float4*)(g_phi + (size_t)gr * F3 + ch * 128 + c0);
                dst[0] = o0;
                dst[1] = o1;
            }
        }
        __syncthreads();
    }
}

// ---------------------------------------------------------------------------
// gather_kernel: one warp per destination node.  Walks its dst-sorted edge
// list in zero-padded batches of 4, accumulates messages in registers,
// writes out = input + acc.  ZERO atomics.
// ---------------------------------------------------------------------------
#define EB 4

__global__ __launch_bounds__(256) void gather_kernel(
        const float* __restrict__ Wr,
        const float* __restrict__ br,
        const float* __restrict__ ns,
        const float* __restrict__ nv,
        float* __restrict__ out) {
    __shared__ float sWr[RBFN * F3 + F3];
    const int tid = threadIdx.x;
    for (int i = tid; i < RBFN * F3; i += 256) sWr[i] = Wr[i];
    for (int i = tid; i < F3; i += 256)        sWr[RBFN * F3 + i] = br[i];
    __syncthreads();

    const float4* Wr4 = (const float4*)sWr;                 // row stride 96 float4
    const float4* br4 = (const float4*)(sWr + RBFN * F3);

    const int lane = tid & 31;
    const int dst  = blockIdx.x * 8 + (tid >> 5);
    const int beg  = g_offs[dst];
    const int end  = g_offs[dst + 1];

    const float4* phi4 = (const float4*)g_phi;
    const float4* nv4  = (const float4*)nv;

    float4 accS  = make_float4(0.f, 0.f, 0.f, 0.f);
    float4 accV0 = accS, accV1 = accS, accV2 = accS;

    for (int k = beg; k < end; k += EB) {
        const int nb = min(EB, end - k);

        // ---- phase A: per-edge geometry (pads are inert: fc=0, d=1) ----
        float fcv[EB], cth[EB], sn[EB], snm1[EB];
        float hx[EB], hy[EB], hz[EB];
        int srcv[EB];
        #pragma unroll
        for (int be = 0; be < EB; be++) {
            float4 rec = (be < nb) ? g_sorted[k + be]
                                   : make_float4(1.f, 0.f, 0.f, __int_as_float(0));
            srcv[be] = __float_as_int(rec.w);
            float rx = rec.x, ry = rec.y, rz = rec.z;
            float d  = sqrtf(rx * rx + ry * ry + rz * rz);
            float id = 1.0f / d;
            float th = d * (PI_F / RCUT);
            float c  = __cosf(th);
            fcv[be]  = (be < nb && d < RCUT) ? 0.5f * (c + 1.0f) : 0.0f;
            cth[be]  = 2.0f * c;
            sn[be]   = __sinf(th) * id;            // sinc_1
            snm1[be] = 0.0f;                       // sinc_0
            hx[be] = rx * id; hy[be] = ry * id; hz[be] = rz * id;
        }

        // ---- phase B: rbf = sinc @ Wr + br, 4 edges share each Wr read ----
        float4 aA[EB], aB[EB], aC[EB];
        {
            float4 bA = br4[lane], bB = br4[32 + lane], bC = br4[64 + lane];
            #pragma unroll
            for (int be = 0; be < EB; be++) { aA[be] = bA; aB[be] = bB; aC[be] = bC; }
        }
        #pragma unroll
        for (int n = 0; n < RBFN; n++) {
            float4 wA = Wr4[n * 96 + lane];
            float4 wB = Wr4[n * 96 + 32 + lane];
            float4 wC = Wr4[n * 96 + 64 + lane];
            #pragma unroll
            for (int be = 0; be < EB; be++) {
                float s = sn[be];
                aA[be].x = fmaf(s, wA.x, aA[be].x);
                aA[be].y = fmaf(s, wA.y, aA[be].y);
                aA[be].z = fmaf(s, wA.z, aA[be].z);
                aA[be].w = fmaf(s, wA.w, aA[be].w);
                aB[be].x = fmaf(s, wB.x, aB[be].x);
                aB[be].y = fmaf(s, wB.y, aB[be].y);
                aB[be].z = fmaf(s, wB.z, aB[be].z);
                aB[be].w = fmaf(s, wB.w, aB[be].w);
                aC[be].x = fmaf(s, wC.x, aC[be].x);
                aC[be].y = fmaf(s, wC.y, aC[be].y);
                aC[be].z = fmaf(s, wC.z, aC[be].z);
                aC[be].w = fmaf(s, wC.w, aC[be].w);
                float nx = fmaf(cth[be], s, -snm1[be]);   // Chebyshev step
                snm1[be] = s;
                sn[be]   = nx;
            }
        }

        // ---- phase C: gather phi/nv[src], accumulate in registers ----
        #pragma unroll
        for (int be = 0; be < EB; be++) {
            float fc = fcv[be];
            if (fc == 0.0f) continue;

            long sb = (long)srcv[be] * 96;
            float4 pA = phi4[sb + lane];
            float4 pB = phi4[sb + 32 + lane];
            float4 pC = phi4[sb + 64 + lane];

            float4 s1, s3;
            s1.x = pA.x * aA[be].x * fc; s1.y = pA.y * aA[be].y * fc;
            s1.z = pA.z * aA[be].z * fc; s1.w = pA.w * aA[be].w * fc;
            accS.x = fmaf(pB.x * aB[be].x, fc, accS.x);
            accS.y = fmaf(pB.y * aB[be].y, fc, accS.y);
            accS.z = fmaf(pB.z * aB[be].z, fc, accS.z);
            accS.w = fmaf(pB.w * aB[be].w, fc, accS.w);
            s3.x = pC.x * aC[be].x * fc; s3.y = pC.y * aC[be].y * fc;
            s3.z = pC.z * aC[be].z * fc; s3.w = pC.w * aC[be].w * fc;

            float4 v0 = nv4[sb + 3 * lane + 0];
            float4 v1 = nv4[sb + 3 * lane + 1];
            float4 v2 = nv4[sb + 3 * lane + 2];

            float bx = hx[be], by = hy[be], bz = hz[be];
            accV0.x = fmaf(s1.x, v0.x, fmaf(s3.x, bx, accV0.x));
            accV0.y = fmaf(s1.x, v0.y, fmaf(s3.x, by, accV0.y));
            accV0.z = fmaf(s1.x, v0.z, fmaf(s3.x, bz, accV0.z));
            accV0.w = fmaf(s1.y, v0.w, fmaf(s3.y, bx, accV0.w));
            accV1.x = fmaf(s1.y, v1.x, fmaf(s3.y, by, accV1.x));
            accV1.y = fmaf(s1.y, v1.y, fmaf(s3.y, bz, accV1.y));
            accV1.z = fmaf(s1.z, v1.z, fmaf(s3.z, bx, accV1.z));
            accV1.w = fmaf(s1.z, v1.w, fmaf(s3.z, by, accV1.w));
            accV2.x = fmaf(s1.z, v2.x, fmaf(s3.z, bz, accV2.x));
            accV2.y = fmaf(s1.w, v2.y, fmaf(s3.w, bx, accV2.y));
            accV2.z = fmaf(s1.w, v2.z, fmaf(s3.w, by, accV2.z));
            accV2.w = fmaf(s1.w, v2.w, fmaf(s3.w, bz, accV2.w));
        }
    }

    // ---- epilogue: out = input + acc (plain coalesced stores) ----
    const float4* ns4 = (const float4*)ns;
    float4* outS = (float4*)out;
    float4* outV = (float4*)(out + (size_t)NNODES * FDIM);

    float4 s = ns4[(size_t)dst * 32 + lane];
    s.x += accS.x; s.y += accS.y; s.z += accS.z; s.w += accS.w;
    outS[(size_t)dst * 32 + lane] = s;

    long vb = (long)dst * 96 + 3 * lane;
    float4 v0 = nv4[vb + 0], v1 = nv4[vb + 1], v2 = nv4[vb + 2];
    v0.x += accV0.x; v0.y += accV0.y; v0.z += accV0.z; v0.w += accV0.w;
    v1.x += accV1.x; v1.y += accV1.y; v1.z += accV1.z; v1.w += accV1.w;
    v2.x += accV2.x; v2.y += accV2.y; v2.z += accV2.z; v2.w += accV2.w;
    outV[vb + 0] = v0;
    outV[vb + 1] = v1;
    outV[vb + 2] = v2;
}

// ---------------------------------------------------------------------------
extern "C" void kernel_launch(void* const* d_in, const int* in_sizes, int n_in,
                              void* d_out, int out_size) {
    const float* ns = (const float*)d_in[0];
    const float* nv = (const float*)d_in[1];
    const float* rv = (const float*)d_in[2];
    const float* W1 = (const float*)d_in[3];
    const float* b1 = (const float*)d_in[4];
    const float* W2 = (const float*)d_in[5];
    const float* b2 = (const float*)d_in[6];
    const float* Wr = (const float*)d_in[7];
    const float* br = (const float*)d_in[8];
    const int2*  ei = (const int2*)d_in[9];
    float* out = (float*)d_out;

    cudaFuncSetAttribute(phi_kernel,
                         cudaFuncAttributeMaxDynamicSharedMemorySize, 131072);

    // per-node phi (independent of the sort pipeline)
    phi_kernel<<<(NNODES + 127) / 128, 256, 131072>>>(ns, W1, b1, W2, b2);

    // counting sort of edges by dst
    zero_cnt_kernel<<<(NNODES + 255) / 256, 256>>>();
    hist_kernel<<<(NEDGES + 255) / 256, 256>>>(ei);
    scan_kernel<<<1, 1024>>>();
    scatter_kernel<<<(NEDGES + 255) / 256, 256>>>(ei, rv);

    // warp-per-dst message accumulation, atomic-free, writes final output
    gather_kernel<<<NNODES / 8, 256>>>(Wr, br, ns, nv, out);
}